// round 5
// baseline (speedup 1.0000x reference)
#include <cuda_runtime.h>
#include <cstdint>
#include <math.h>

// ---------------------------------------------------------------------------
// SelfAttention on GB300 (compute_103 PTX target), Round 5:
// mma.sync m16n8k8 tf32, CTA tile 256x128x32, warp tile 64x64 (4x8 frags).
// 3-slot cp.async pipeline: ONE __syncthreads per k-tile, 2-deep prefetch.
//
// out = softmax((xWq^T)(xWk^T)^T / 32) @ (xWv^T) + (xWv^T)
// All GEMMs as NT: C[M,N] = scale * A[M,K] * B[N,K]^T (+R).
// ---------------------------------------------------------------------------

#define BATCH 4
#define SEQ   2048
#define DIM   1024

#define BM 256
#define BN 128
#define BK 32
#define LDS_ROW 36                                  // BK + 4 pad (floats)
#define A_FLOATS (BM * LDS_ROW)                     // 9216
#define B_FLOATS (BN * LDS_ROW)                     // 4608
#define STAGE_FLOATS (A_FLOATS + B_FLOATS)          // 13824
#define STAGES 3
#define SMEM_BYTES (STAGES * STAGE_FLOATS * 4)      // 165888 B

__device__ float g_q [(size_t)BATCH * SEQ * DIM];
__device__ float g_k [(size_t)BATCH * SEQ * DIM];
__device__ float g_v [(size_t)BATCH * SEQ * DIM];
__device__ float g_vt[(size_t)BATCH * DIM * SEQ];
__device__ float g_s [(size_t)BATCH * SEQ * SEQ];
__device__ float g_xr[(size_t)BATCH * SEQ * DIM];
__device__ float g_wq[(size_t)DIM * DIM];
__device__ float g_wk[(size_t)DIM * DIM];
__device__ float g_wv[(size_t)DIM * DIM];

__device__ __forceinline__ float round_tf32(float x) {
    uint32_t u;
    asm("cvt.rna.tf32.f32 %0, %1;" : "=r"(u) : "f"(x));
    return __uint_as_float(u);
}

#define CP16(dst_u32, src_ptr) \
    asm volatile("cp.async.cg.shared.global [%0], [%1], 16;" :: "r"(dst_u32), "l"(src_ptr) : "memory")
#define CP_COMMIT() asm volatile("cp.async.commit_group;" ::: "memory")
#define CP_WAIT(n)  asm volatile("cp.async.wait_group %0;" :: "n"(n) : "memory")

// ---------------------------------------------------------------------------
// C[M,N] = scale * A[M,K] * B[N,K]^T (+ R), tf32 tensor cores.
// ---------------------------------------------------------------------------
__global__ void __launch_bounds__(256, 1) mma_gemm_nt(
    const float* __restrict__ A, const float* __restrict__ B,
    const float* __restrict__ R, float* __restrict__ C,
    int lda, int ldb, int ldc, int KT, float scale, int round_out,
    long long sA, long long sB, long long sR, long long sC)
{
    extern __shared__ float sm[];

    const int tid  = threadIdx.x;
    const int lane = tid & 31;
    const int wid  = tid >> 5;
    const int wm   = wid >> 1;   // 0..3  (64-row slab)
    const int wn   = wid & 1;    // 0..1  (64-col slab)
    const int g    = lane >> 2;  // 0..7
    const int t    = lane & 3;   // 0..3

    A += (long long)blockIdx.z * sA + (long long)(blockIdx.y * BM) * lda;
    B += (long long)blockIdx.z * sB + (long long)(blockIdx.x * BN) * ldb;

    const uint32_t sm_u32 = (uint32_t)__cvta_generic_to_shared(sm);

    float acc[4][8][4] = {};

    // loader: 256 threads; A tile 256x32 = 2048 float4 (8/thr), B 128x32 = 1024 (4/thr)
    auto load_stage = [&](int kt, int s) {
        const uint32_t stA = sm_u32 + (uint32_t)s * (STAGE_FLOATS * 4);
        const uint32_t stB = stA + A_FLOATS * 4;
        const int k0 = kt * BK;
        #pragma unroll
        for (int i = 0; i < 8; i++) {
            int f   = i * 256 + tid;      // 0..2047
            int row = f >> 3;             // 0..255
            int c4  = (f & 7) << 2;       // 0,4,..,28
            CP16(stA + (uint32_t)(row * LDS_ROW + c4) * 4, A + (long long)row * lda + k0 + c4);
        }
        #pragma unroll
        for (int i = 0; i < 4; i++) {
            int f   = i * 256 + tid;      // 0..1023
            int row = f >> 3;             // 0..127
            int c4  = (f & 7) << 2;
            CP16(stB + (uint32_t)(row * LDS_ROW + c4) * 4, B + (long long)row * ldb + k0 + c4);
        }
        CP_COMMIT();
    };

    // prologue: fill two of three slots (groups 0,1)
    load_stage(0, 0);
    load_stage(1, 1);

    for (int kt = 0; kt < KT; kt++) {
        const int cur = kt % STAGES;

        // group kt must be complete before reading slot cur
        if (kt + 1 < KT) { CP_WAIT(1); }
        else             { CP_WAIT(0); }
        __syncthreads();   // also proves everyone finished reading slot (kt+2)%STAGES at iter kt-1

        // prefetch kt+2 into the slot last read at iter kt-1
        if (kt + 2 < KT) load_stage(kt + 2, (kt + 2) % STAGES);

        const float* pA = sm + cur * STAGE_FLOATS + (wm * 64) * LDS_ROW;
        const float* pB = sm + cur * STAGE_FLOATS + A_FLOATS + (wn * 64) * LDS_ROW;

        #pragma unroll
        for (int kk = 0; kk < 4; kk++) {
            const int kb = kk * 8;
            uint32_t af[4][4], bf[8][2];
            #pragma unroll
            for (int mt = 0; mt < 4; mt++) {
                const float* r0 = pA + (mt * 16 + g) * LDS_ROW + kb + t;
                const float* r1 = r0 + 8 * LDS_ROW;
                af[mt][0] = __float_as_uint(r0[0]);
                af[mt][1] = __float_as_uint(r1[0]);
                af[mt][2] = __float_as_uint(r0[4]);
                af[mt][3] = __float_as_uint(r1[4]);
            }
            #pragma unroll
            for (int nt = 0; nt < 8; nt++) {
                const float* c0 = pB + (nt * 8 + g) * LDS_ROW + kb + t;
                bf[nt][0] = __float_as_uint(c0[0]);
                bf[nt][1] = __float_as_uint(c0[4]);
            }
            #pragma unroll
            for (int mt = 0; mt < 4; mt++)
                #pragma unroll
                for (int nt = 0; nt < 8; nt++)
                    asm volatile(
                        "mma.sync.aligned.m16n8k8.row.col.f32.tf32.tf32.f32 "
                        "{%0,%1,%2,%3}, {%4,%5,%6,%7}, {%8,%9}, {%0,%1,%2,%3};"
                        : "+f"(acc[mt][nt][0]), "+f"(acc[mt][nt][1]),
                          "+f"(acc[mt][nt][2]), "+f"(acc[mt][nt][3])
                        : "r"(af[mt][0]), "r"(af[mt][1]), "r"(af[mt][2]), "r"(af[mt][3]),
                          "r"(bf[nt][0]), "r"(bf[nt][1]));
        }
    }

    // epilogue
    float* Cb = C + (long long)blockIdx.z * sC
                  + (long long)(blockIdx.y * BM + wm * 64) * ldc + blockIdx.x * BN + wn * 64;
    const float* Rb = R ? (R + (long long)blockIdx.z * sR
                  + (long long)(blockIdx.y * BM + wm * 64) * ldc + blockIdx.x * BN + wn * 64)
                        : nullptr;

    #pragma unroll
    for (int mt = 0; mt < 4; mt++) {
        #pragma unroll
        for (int nt = 0; nt < 8; nt++) {
            const int r0 = mt * 16 + g;
            const int c0 = nt * 8 + t * 2;
            float v0 = acc[mt][nt][0] * scale;
            float v1 = acc[mt][nt][1] * scale;
            float v2 = acc[mt][nt][2] * scale;
            float v3 = acc[mt][nt][3] * scale;
            if (Rb) {
                v0 += Rb[(long long)r0 * ldc + c0];
                v1 += Rb[(long long)r0 * ldc + c0 + 1];
                v2 += Rb[(long long)(r0 + 8) * ldc + c0];
                v3 += Rb[(long long)(r0 + 8) * ldc + c0 + 1];
            }
            if (round_out) {
                v0 = round_tf32(v0); v1 = round_tf32(v1);
                v2 = round_tf32(v2); v3 = round_tf32(v3);
            }
            *(float2*)&Cb[(long long)r0 * ldc + c0]       = make_float2(v0, v1);
            *(float2*)&Cb[(long long)(r0 + 8) * ldc + c0] = make_float2(v2, v3);
        }
    }
}

// ---------------- round fp32 array to tf32 (rna) ----------------
__global__ void __launch_bounds__(256) round_arr(const float* __restrict__ in,
                                                 float* __restrict__ out)
{
    long long i = ((long long)blockIdx.x * 256 + threadIdx.x) * 4;
    float4 v = *(const float4*)&in[i];
    v.x = round_tf32(v.x); v.y = round_tf32(v.y);
    v.z = round_tf32(v.z); v.w = round_tf32(v.w);
    *(float4*)&out[i] = v;
}

// ---------------- transpose: vt[b][n][j] = v[b][j][n] ----------------
__global__ void __launch_bounds__(256) transpose_v(const float* __restrict__ v,
                                                   float* __restrict__ vt)
{
    __shared__ float t[32][33];
    const long long bi = (long long)blockIdx.z * SEQ * DIM;
    const long long bo = (long long)blockIdx.z * DIM * SEQ;
    int x = blockIdx.x * 32 + threadIdx.x;   // n
    int y = blockIdx.y * 32 + threadIdx.y;   // j
    #pragma unroll
    for (int i = 0; i < 32; i += 8)
        t[threadIdx.y + i][threadIdx.x] = v[bi + (long long)(y + i) * DIM + x];
    __syncthreads();
    int xo = blockIdx.y * 32 + threadIdx.x;  // j
    int yo = blockIdx.x * 32 + threadIdx.y;  // n
    #pragma unroll
    for (int i = 0; i < 32; i += 8)
        vt[bo + (long long)(yo + i) * SEQ + xo] = t[threadIdx.x][threadIdx.y + i];
}

// ---------------- row softmax (2048 cols), writes tf32-rounded probs --------
__global__ void __launch_bounds__(256) softmax_rows(float* __restrict__ S)
{
    long long row = blockIdx.x;
    float* p = S + row * SEQ;
    int tid = threadIdx.x;
    __shared__ float red[256];

    float v[8];
    float mx = -INFINITY;
    #pragma unroll
    for (int i = 0; i < 8; i++) { v[i] = p[tid + i * 256]; mx = fmaxf(mx, v[i]); }
    red[tid] = mx; __syncthreads();
    #pragma unroll
    for (int s = 128; s > 0; s >>= 1) { if (tid < s) red[tid] = fmaxf(red[tid], red[tid + s]); __syncthreads(); }
    mx = red[0]; __syncthreads();

    float sum = 0.f;
    #pragma unroll
    for (int i = 0; i < 8; i++) { v[i] = __expf(v[i] - mx); sum += v[i]; }
    red[tid] = sum; __syncthreads();
    #pragma unroll
    for (int s = 128; s > 0; s >>= 1) { if (tid < s) red[tid] += red[tid + s]; __syncthreads(); }
    float inv = 1.0f / red[0];
    #pragma unroll
    for (int i = 0; i < 8; i++) p[tid + i * 256] = round_tf32(v[i] * inv);
}

extern "C" void kernel_launch(void* const* d_in, const int* in_sizes, int n_in,
                              void* d_out, int out_size)
{
    const float* x  = (const float*)d_in[0];
    const float* Wq = (const float*)d_in[1];
    const float* Wk = (const float*)d_in[2];
    const float* Wv = (const float*)d_in[3];
    float* out = (float*)d_out;

    float *q, *k, *v, *vt, *s, *xr, *wq, *wk, *wv;
    cudaGetSymbolAddress((void**)&q,  g_q);
    cudaGetSymbolAddress((void**)&k,  g_k);
    cudaGetSymbolAddress((void**)&v,  g_v);
    cudaGetSymbolAddress((void**)&vt, g_vt);
    cudaGetSymbolAddress((void**)&s,  g_s);
    cudaGetSymbolAddress((void**)&xr, g_xr);
    cudaGetSymbolAddress((void**)&wq, g_wq);
    cudaGetSymbolAddress((void**)&wk, g_wk);
    cudaGetSymbolAddress((void**)&wv, g_wv);

    cudaFuncSetAttribute(mma_gemm_nt, cudaFuncAttributeMaxDynamicSharedMemorySize, SMEM_BYTES);

    const int M = BATCH * SEQ;   // 8192

    // Pre-round inputs to tf32 (rna, unbiased)
    round_arr<<<(M * DIM) / 1024, 256>>>(x, xr);
    round_arr<<<(DIM * DIM) / 1024, 256>>>(Wq, wq);
    round_arr<<<(DIM * DIM) / 1024, 256>>>(Wk, wk);
    round_arr<<<(DIM * DIM) / 1024, 256>>>(Wv, wv);

    // QKV projections: [8192,1024] = xr @ W^T, K=1024 (32 k-tiles), round outputs
    dim3 gP(DIM / BN, M / BM, 1);   // (8, 32)
    mma_gemm_nt<<<gP, 256, SMEM_BYTES>>>(xr, wq, nullptr, q, DIM, DIM, DIM, 32, 1.0f, 1, 0, 0, 0, 0);
    mma_gemm_nt<<<gP, 256, SMEM_BYTES>>>(xr, wk, nullptr, k, DIM, DIM, DIM, 32, 1.0f, 1, 0, 0, 0, 0);
    mma_gemm_nt<<<gP, 256, SMEM_BYTES>>>(xr, wv, nullptr, v, DIM, DIM, DIM, 32, 1.0f, 1, 0, 0, 0, 0);

    // V transpose for PV gemm
    dim3 gT(DIM / 32, SEQ / 32, BATCH);
    transpose_v<<<gT, dim3(32, 8)>>>(v, vt);

    // Scores: per batch S = (1/32) q @ k^T, [2048,2048], K=1024
    dim3 gS(SEQ / BN, SEQ / BM, BATCH);   // (16, 8, 4)
    mma_gemm_nt<<<gS, 256, SMEM_BYTES>>>(q, k, nullptr, s, DIM, DIM, SEQ, 32, 0.03125f, 0,
                                         (long long)SEQ * DIM, (long long)SEQ * DIM, 0,
                                         (long long)SEQ * SEQ);

    // Softmax (writes tf32-rounded probabilities)
    softmax_rows<<<BATCH * SEQ, 256>>>(s);

    // Output: att = S @ v + v  ->  NT with B = vt [1024 x 2048], K=2048 (64 k-tiles)
    dim3 gO(DIM / BN, SEQ / BM, BATCH);   // (8, 8, 4)
    mma_gemm_nt<<<gO, 256, SMEM_BYTES>>>(s, vt, v, out, SEQ, SEQ, DIM, 64, 1.0f, 0,
                                         (long long)SEQ * SEQ, (long long)DIM * SEQ,
                                         (long long)SEQ * DIM, (long long)SEQ * DIM);
}

// round 6
// speedup vs baseline: 1.7979x; 1.7979x over previous
#include <cuda_runtime.h>
#include <cuda_fp16.h>
#include <cstdint>
#include <math.h>

// ---------------------------------------------------------------------------
// SelfAttention on GB300 (compute_103 PTX target), Round 6:
// fp16 tensor cores (mma.sync m16n8k16 f16, fp32 accumulate).
// CTA tile 256x128x64, warp tile 64x64, 3-slot cp.async pipeline,
// one __syncthreads per k-tile. All intermediates fp16 (same 10-bit mantissa
// as the tf32 chain that measured rel_err=3.47e-4), output fp32.
//
// out = softmax((xWq^T)(xWk^T)^T / 32) @ (xWv^T) + (xWv^T)
// All GEMMs as NT: C[M,N] = scale * A[M,K] * B[N,K]^T (+R).
// ---------------------------------------------------------------------------

#define BATCH 4
#define SEQ   2048
#define DIM   1024

#define BM 256
#define BN 128
#define BK 64
#define LROW 72                                     // BK + 8 pad (halves)
#define A_HALVES (BM * LROW)                        // 18432
#define B_HALVES (BN * LROW)                        // 9216
#define STAGE_HALVES (A_HALVES + B_HALVES)          // 27648
#define STAGES 3
#define SMEM_BYTES (STAGES * STAGE_HALVES * 2)      // 165888 B

__device__ __half g_q [(size_t)BATCH * SEQ * DIM];
__device__ __half g_k [(size_t)BATCH * SEQ * DIM];
__device__ __half g_v [(size_t)BATCH * SEQ * DIM];
__device__ __half g_vt[(size_t)BATCH * DIM * SEQ];
__device__ __half g_s [(size_t)BATCH * SEQ * SEQ];
__device__ __half g_xh[(size_t)BATCH * SEQ * DIM];
__device__ __half g_wq[(size_t)DIM * DIM];
__device__ __half g_wk[(size_t)DIM * DIM];
__device__ __half g_wv[(size_t)DIM * DIM];

#define CP16(dst_u32, src_ptr) \
    asm volatile("cp.async.cg.shared.global [%0], [%1], 16;" :: "r"(dst_u32), "l"(src_ptr) : "memory")
#define CP_COMMIT() asm volatile("cp.async.commit_group;" ::: "memory")
#define CP_WAIT(n)  asm volatile("cp.async.wait_group %0;" :: "n"(n) : "memory")

// ---------------------------------------------------------------------------
// C[M,N] = scale * A[M,K] * B[N,K]^T (+ R), fp16 in, fp32 accumulate.
// Exactly one of Cf / Ch is non-null (fp32 or fp16 output).
// ---------------------------------------------------------------------------
__global__ void __launch_bounds__(256, 1) hmma_gemm_nt(
    const __half* __restrict__ A, const __half* __restrict__ B,
    const __half* __restrict__ R, float* __restrict__ Cf, __half* __restrict__ Ch,
    int lda, int ldb, int ldc, int KT, float scale,
    long long sA, long long sB, long long sR, long long sC)
{
    extern __shared__ __half sm[];

    const int tid  = threadIdx.x;
    const int lane = tid & 31;
    const int wid  = tid >> 5;
    const int wm   = wid >> 1;   // 0..3  (64-row slab)
    const int wn   = wid & 1;    // 0..1  (64-col slab)
    const int g    = lane >> 2;  // 0..7
    const int t    = lane & 3;   // 0..3

    A += (long long)blockIdx.z * sA + (long long)(blockIdx.y * BM) * lda;
    B += (long long)blockIdx.z * sB + (long long)(blockIdx.x * BN) * ldb;

    const uint32_t sm_u32 = (uint32_t)__cvta_generic_to_shared(sm);

    float acc[4][8][4] = {};

    // loader: A 256x64 halves = 2048 16B-chunks (8/thr); B 128x64 = 1024 (4/thr)
    auto load_stage = [&](int kt, int s) {
        const uint32_t stA = sm_u32 + (uint32_t)s * (STAGE_HALVES * 2);
        const uint32_t stB = stA + A_HALVES * 2;
        const int k0 = kt * BK;
        #pragma unroll
        for (int i = 0; i < 8; i++) {
            int f   = i * 256 + tid;      // 0..2047
            int row = f >> 3;             // 0..255
            int c8  = (f & 7) << 3;       // 0,8,..,56 (halves)
            CP16(stA + (uint32_t)(row * LROW + c8) * 2, A + (long long)row * lda + k0 + c8);
        }
        #pragma unroll
        for (int i = 0; i < 4; i++) {
            int f   = i * 256 + tid;      // 0..1023
            int row = f >> 3;             // 0..127
            int c8  = (f & 7) << 3;
            CP16(stB + (uint32_t)(row * LROW + c8) * 2, B + (long long)row * ldb + k0 + c8);
        }
        CP_COMMIT();
    };

    load_stage(0, 0);
    load_stage(1, 1);

    for (int kt = 0; kt < KT; kt++) {
        const int cur = kt % STAGES;

        if (kt + 1 < KT) { CP_WAIT(1); }
        else             { CP_WAIT(0); }
        __syncthreads();

        if (kt + 2 < KT) load_stage(kt + 2, (kt + 2) % STAGES);

        const __half* pA = sm + cur * STAGE_HALVES + (wm * 64) * LROW;
        const __half* pB = sm + cur * STAGE_HALVES + A_HALVES + (wn * 64) * LROW;

        #pragma unroll
        for (int kk = 0; kk < 4; kk++) {
            const int kb = kk * 16;       // halves
            uint32_t af[4][4], bf[8][2];
            #pragma unroll
            for (int mt = 0; mt < 4; mt++) {
                const __half* r0 = pA + (mt * 16 + g) * LROW + kb + 2 * t;
                af[mt][0] = *(const uint32_t*)(r0);
                af[mt][1] = *(const uint32_t*)(r0 + 8 * LROW);
                af[mt][2] = *(const uint32_t*)(r0 + 8);
                af[mt][3] = *(const uint32_t*)(r0 + 8 * LROW + 8);
            }
            #pragma unroll
            for (int nt = 0; nt < 8; nt++) {
                const __half* c0 = pB + (nt * 8 + g) * LROW + kb + 2 * t;
                bf[nt][0] = *(const uint32_t*)(c0);
                bf[nt][1] = *(const uint32_t*)(c0 + 8);
            }
            #pragma unroll
            for (int mt = 0; mt < 4; mt++)
                #pragma unroll
                for (int nt = 0; nt < 8; nt++)
                    asm volatile(
                        "mma.sync.aligned.m16n8k16.row.col.f32.f16.f16.f32 "
                        "{%0,%1,%2,%3}, {%4,%5,%6,%7}, {%8,%9}, {%0,%1,%2,%3};"
                        : "+f"(acc[mt][nt][0]), "+f"(acc[mt][nt][1]),
                          "+f"(acc[mt][nt][2]), "+f"(acc[mt][nt][3])
                        : "r"(af[mt][0]), "r"(af[mt][1]), "r"(af[mt][2]), "r"(af[mt][3]),
                          "r"(bf[nt][0]), "r"(bf[nt][1]));
        }
    }

    // epilogue
    const long long rowBase = (long long)(blockIdx.y * BM + wm * 64);
    const long long colBase = blockIdx.x * BN + wn * 64;

    #pragma unroll
    for (int mt = 0; mt < 4; mt++) {
        #pragma unroll
        for (int nt = 0; nt < 8; nt++) {
            const long long r0 = rowBase + mt * 16 + g;
            const long long c0 = colBase + nt * 8 + t * 2;
            float v0 = acc[mt][nt][0] * scale;
            float v1 = acc[mt][nt][1] * scale;
            float v2 = acc[mt][nt][2] * scale;
            float v3 = acc[mt][nt][3] * scale;
            if (Cf) {
                float* Cb = Cf + (long long)blockIdx.z * sC;
                if (R) {
                    const __half* Rb = R + (long long)blockIdx.z * sR;
                    v0 += __half2float(Rb[r0 * ldc + c0]);
                    v1 += __half2float(Rb[r0 * ldc + c0 + 1]);
                    v2 += __half2float(Rb[(r0 + 8) * ldc + c0]);
                    v3 += __half2float(Rb[(r0 + 8) * ldc + c0 + 1]);
                }
                *(float2*)&Cb[r0 * ldc + c0]       = make_float2(v0, v1);
                *(float2*)&Cb[(r0 + 8) * ldc + c0] = make_float2(v2, v3);
            } else {
                __half* Cb = Ch + (long long)blockIdx.z * sC;
                *(__half2*)&Cb[r0 * ldc + c0]       = __floats2half2_rn(v0, v1);
                *(__half2*)&Cb[(r0 + 8) * ldc + c0] = __floats2half2_rn(v2, v3);
            }
        }
    }
}

// ---------------- fp32 -> fp16 conversion (8 elems/thread) ----------------
__global__ void __launch_bounds__(256) f32_to_f16(const float* __restrict__ in,
                                                  __half* __restrict__ out)
{
    long long i = ((long long)blockIdx.x * 256 + threadIdx.x) * 8;
    float4 a = *(const float4*)&in[i];
    float4 b = *(const float4*)&in[i + 4];
    __half2 h0 = __floats2half2_rn(a.x, a.y);
    __half2 h1 = __floats2half2_rn(a.z, a.w);
    __half2 h2 = __floats2half2_rn(b.x, b.y);
    __half2 h3 = __floats2half2_rn(b.z, b.w);
    uint4 u;
    u.x = *(uint32_t*)&h0; u.y = *(uint32_t*)&h1;
    u.z = *(uint32_t*)&h2; u.w = *(uint32_t*)&h3;
    *(uint4*)&out[i] = u;
}

// ---------------- transpose: vt[b][n][j] = v[b][j][n] (fp16) ----------------
__global__ void __launch_bounds__(256) transpose_v(const __half* __restrict__ v,
                                                   __half* __restrict__ vt)
{
    __shared__ __half t[32][33];
    const long long bi = (long long)blockIdx.z * SEQ * DIM;
    const long long bo = (long long)blockIdx.z * DIM * SEQ;
    int x = blockIdx.x * 32 + threadIdx.x;   // n
    int y = blockIdx.y * 32 + threadIdx.y;   // j
    #pragma unroll
    for (int i = 0; i < 32; i += 8)
        t[threadIdx.y + i][threadIdx.x] = v[bi + (long long)(y + i) * DIM + x];
    __syncthreads();
    int xo = blockIdx.y * 32 + threadIdx.x;  // j
    int yo = blockIdx.x * 32 + threadIdx.y;  // n
    #pragma unroll
    for (int i = 0; i < 32; i += 8)
        vt[bo + (long long)(yo + i) * SEQ + xo] = t[threadIdx.x][threadIdx.y + i];
}

// ---------------- row softmax (2048 cols, fp16 in/out, fp32 math) ----------
__global__ void __launch_bounds__(256) softmax_rows(__half* __restrict__ S)
{
    long long row = blockIdx.x;
    __half* p = S + row * SEQ;
    int tid = threadIdx.x;
    __shared__ float red[256];

    float v[8];
    float mx = -INFINITY;
    #pragma unroll
    for (int i = 0; i < 8; i++) { v[i] = __half2float(p[tid + i * 256]); mx = fmaxf(mx, v[i]); }
    red[tid] = mx; __syncthreads();
    #pragma unroll
    for (int s = 128; s > 0; s >>= 1) { if (tid < s) red[tid] = fmaxf(red[tid], red[tid + s]); __syncthreads(); }
    mx = red[0]; __syncthreads();

    float sum = 0.f;
    #pragma unroll
    for (int i = 0; i < 8; i++) { v[i] = __expf(v[i] - mx); sum += v[i]; }
    red[tid] = sum; __syncthreads();
    #pragma unroll
    for (int s = 128; s > 0; s >>= 1) { if (tid < s) red[tid] += red[tid + s]; __syncthreads(); }
    float inv = 1.0f / red[0];
    #pragma unroll
    for (int i = 0; i < 8; i++) p[tid + i * 256] = __float2half_rn(v[i] * inv);
}

extern "C" void kernel_launch(void* const* d_in, const int* in_sizes, int n_in,
                              void* d_out, int out_size)
{
    const float* x  = (const float*)d_in[0];
    const float* Wq = (const float*)d_in[1];
    const float* Wk = (const float*)d_in[2];
    const float* Wv = (const float*)d_in[3];
    float* out = (float*)d_out;

    __half *q, *k, *v, *vt, *s, *xh, *wq, *wk, *wv;
    cudaGetSymbolAddress((void**)&q,  g_q);
    cudaGetSymbolAddress((void**)&k,  g_k);
    cudaGetSymbolAddress((void**)&v,  g_v);
    cudaGetSymbolAddress((void**)&vt, g_vt);
    cudaGetSymbolAddress((void**)&s,  g_s);
    cudaGetSymbolAddress((void**)&xh, g_xh);
    cudaGetSymbolAddress((void**)&wq, g_wq);
    cudaGetSymbolAddress((void**)&wk, g_wk);
    cudaGetSymbolAddress((void**)&wv, g_wv);

    cudaFuncSetAttribute(hmma_gemm_nt, cudaFuncAttributeMaxDynamicSharedMemorySize, SMEM_BYTES);

    const int M = BATCH * SEQ;   // 8192

    // fp32 -> fp16 conversion of inputs
    f32_to_f16<<<(M * DIM) / 2048, 256>>>(x, xh);
    f32_to_f16<<<(DIM * DIM) / 2048, 256>>>(Wq, wq);
    f32_to_f16<<<(DIM * DIM) / 2048, 256>>>(Wk, wk);
    f32_to_f16<<<(DIM * DIM) / 2048, 256>>>(Wv, wv);

    // QKV projections: [8192,1024] = xh @ W^T, K=1024 (16 k-tiles), fp16 out
    dim3 gP(DIM / BN, M / BM, 1);   // (8, 32)
    hmma_gemm_nt<<<gP, 256, SMEM_BYTES>>>(xh, wq, nullptr, nullptr, q, DIM, DIM, DIM, 16, 1.0f, 0, 0, 0, 0);
    hmma_gemm_nt<<<gP, 256, SMEM_BYTES>>>(xh, wk, nullptr, nullptr, k, DIM, DIM, DIM, 16, 1.0f, 0, 0, 0, 0);
    hmma_gemm_nt<<<gP, 256, SMEM_BYTES>>>(xh, wv, nullptr, nullptr, v, DIM, DIM, DIM, 16, 1.0f, 0, 0, 0, 0);

    // V transpose for PV gemm
    dim3 gT(DIM / 32, SEQ / 32, BATCH);
    transpose_v<<<gT, dim3(32, 8)>>>(v, vt);

    // Scores: per batch S = (1/32) q @ k^T, [2048,2048], K=1024, fp16 out
    dim3 gS(SEQ / BN, SEQ / BM, BATCH);   // (16, 8, 4)
    hmma_gemm_nt<<<gS, 256, SMEM_BYTES>>>(q, k, nullptr, nullptr, s, DIM, DIM, SEQ, 16, 0.03125f,
                                          (long long)SEQ * DIM, (long long)SEQ * DIM, 0,
                                          (long long)SEQ * SEQ);

    softmax_rows<<<BATCH * SEQ, 256>>>(s);

    // Output: att = S @ v + v  ->  NT with B = vt [1024 x 2048], K=2048 (32 k-tiles), fp32 out
    dim3 gO(DIM / BN, SEQ / BM, BATCH);   // (8, 8, 4)
    hmma_gemm_nt<<<gO, 256, SMEM_BYTES>>>(s, vt, v, out, nullptr, SEQ, SEQ, DIM, 32, 1.0f,
                                          (long long)SEQ * SEQ, (long long)DIM * SEQ,
                                          (long long)SEQ * DIM, (long long)SEQ * DIM);
}

// round 7
// speedup vs baseline: 1.8297x; 1.0177x over previous
#include <cuda_runtime.h>
#include <cuda_fp16.h>
#include <cstdint>
#include <math.h>

// ---------------------------------------------------------------------------
// SelfAttention on GB300 (compute_103 PTX target), Round 7:
// fp16 mma.sync m16n8k16 + ldmatrix fragment loads + fused QKV projection.
// CTA tile 256x128x64, warp tile 64x64, 3-slot cp.async pipeline.
//
// out = softmax((xWq^T)(xWk^T)^T / 32) @ (xWv^T) + (xWv^T)
// All GEMMs as NT: C[M,N] = scale * A[M,K] * B[N,K]^T (+R).
// ---------------------------------------------------------------------------

#define BATCH 4
#define SEQ   2048
#define DIM   1024
#define QKVLD 3072                                  // fused q|k|v row stride

#define BM 256
#define BN 128
#define BK 64
#define LROW 72                                     // BK + 8 pad (halves)
#define A_HALVES (BM * LROW)                        // 18432
#define B_HALVES (BN * LROW)                        // 9216
#define STAGE_HALVES (A_HALVES + B_HALVES)          // 27648
#define STAGES 3
#define SMEM_BYTES (STAGES * STAGE_HALVES * 2)      // 165888 B

__device__ __half g_qkv[(size_t)BATCH * SEQ * QKVLD];   // [8192][3072] = q|k|v
__device__ __half g_vt [(size_t)BATCH * DIM * SEQ];
__device__ __half g_s  [(size_t)BATCH * SEQ * SEQ];
__device__ __half g_xh [(size_t)BATCH * SEQ * DIM];
__device__ __half g_w  [(size_t)3 * DIM * DIM];         // Wq|Wk|Wv rows

#define CP16(dst_u32, src_ptr) \
    asm volatile("cp.async.cg.shared.global [%0], [%1], 16;" :: "r"(dst_u32), "l"(src_ptr) : "memory")
#define CP_COMMIT() asm volatile("cp.async.commit_group;" ::: "memory")
#define CP_WAIT(n)  asm volatile("cp.async.wait_group %0;" :: "n"(n) : "memory")

#define LDSM_X4(r0, r1, r2, r3, addr) \
    asm volatile("ldmatrix.sync.aligned.m8n8.x4.shared.b16 {%0,%1,%2,%3}, [%4];" \
        : "=r"(r0), "=r"(r1), "=r"(r2), "=r"(r3) : "r"(addr))

// ---------------------------------------------------------------------------
// C[M,N] = scale * A[M,K] * B[N,K]^T (+ R), fp16 in, fp32 accumulate.
// Exactly one of Cf / Ch is non-null.
// ---------------------------------------------------------------------------
__global__ void __launch_bounds__(256, 1) hmma_gemm_nt(
    const __half* __restrict__ A, const __half* __restrict__ B,
    const __half* __restrict__ R, float* __restrict__ Cf, __half* __restrict__ Ch,
    int lda, int ldb, int ldc, int ldr, int KT, float scale,
    long long sA, long long sB, long long sR, long long sC)
{
    extern __shared__ __half sm[];

    const int tid  = threadIdx.x;
    const int lane = tid & 31;
    const int wid  = tid >> 5;
    const int wm   = wid >> 1;   // 0..3  (64-row slab)
    const int wn   = wid & 1;    // 0..1  (64-col slab)
    const int g    = lane >> 2;  // 0..7
    const int t    = lane & 3;   // 0..3

    A += (long long)blockIdx.z * sA + (long long)(blockIdx.y * BM) * lda;
    B += (long long)blockIdx.z * sB + (long long)(blockIdx.x * BN) * ldb;

    const uint32_t sm_u32 = (uint32_t)__cvta_generic_to_shared(sm);

    float acc[4][8][4] = {};

    // loader: A 256x64 halves = 2048 16B-chunks (8/thr); B 128x64 = 1024 (4/thr)
    auto load_stage = [&](int kt, int s) {
        const uint32_t stA = sm_u32 + (uint32_t)s * (STAGE_HALVES * 2);
        const uint32_t stB = stA + A_HALVES * 2;
        const int k0 = kt * BK;
        #pragma unroll
        for (int i = 0; i < 8; i++) {
            int f   = i * 256 + tid;      // 0..2047
            int row = f >> 3;             // 0..255
            int c8  = (f & 7) << 3;       // 0,8,..,56 (halves)
            CP16(stA + (uint32_t)(row * LROW + c8) * 2, A + (long long)row * lda + k0 + c8);
        }
        #pragma unroll
        for (int i = 0; i < 4; i++) {
            int f   = i * 256 + tid;      // 0..1023
            int row = f >> 3;             // 0..127
            int c8  = (f & 7) << 3;
            CP16(stB + (uint32_t)(row * LROW + c8) * 2, B + (long long)row * ldb + k0 + c8);
        }
        CP_COMMIT();
    };

    load_stage(0, 0);
    load_stage(1, 1);

    // ldmatrix per-lane base offsets (bytes), relative to stage base
    // A: lanes 0-15 -> rows (lane&15) @k+0 ; lanes 16-31 -> same rows @k+8
    const uint32_t aOff = (uint32_t)((wm * 64 + (lane & 15)) * LROW + ((lane >> 4) << 3)) * 2;
    // B: quadrants (n, n, n+8, n+8) x (k+0, k+8, k+0, k+8)
    const uint32_t bOff = (uint32_t)(A_HALVES
                        + (wn * 64 + (lane & 7) + ((lane & 16) >> 1)) * LROW + (lane & 8)) * 2;

    for (int kt = 0; kt < KT; kt++) {
        const int cur = kt % STAGES;

        if (kt + 1 < KT) { CP_WAIT(1); }
        else             { CP_WAIT(0); }
        __syncthreads();

        if (kt + 2 < KT) load_stage(kt + 2, (kt + 2) % STAGES);

        const uint32_t stg = sm_u32 + (uint32_t)cur * (STAGE_HALVES * 2);
        const uint32_t aLane = stg + aOff;
        const uint32_t bLane = stg + bOff;

        #pragma unroll
        for (int kk = 0; kk < 4; kk++) {
            const int kb = kk * 16;       // halves
            uint32_t af[4][4], bf[8][2];
            #pragma unroll
            for (int mt = 0; mt < 4; mt++)
                LDSM_X4(af[mt][0], af[mt][1], af[mt][2], af[mt][3],
                        aLane + (uint32_t)(mt * 16 * LROW + kb) * 2);
            #pragma unroll
            for (int p = 0; p < 4; p++)
                LDSM_X4(bf[2 * p][0], bf[2 * p][1], bf[2 * p + 1][0], bf[2 * p + 1][1],
                        bLane + (uint32_t)(p * 16 * LROW + kb) * 2);
            #pragma unroll
            for (int mt = 0; mt < 4; mt++)
                #pragma unroll
                for (int nt = 0; nt < 8; nt++)
                    asm volatile(
                        "mma.sync.aligned.m16n8k16.row.col.f32.f16.f16.f32 "
                        "{%0,%1,%2,%3}, {%4,%5,%6,%7}, {%8,%9}, {%0,%1,%2,%3};"
                        : "+f"(acc[mt][nt][0]), "+f"(acc[mt][nt][1]),
                          "+f"(acc[mt][nt][2]), "+f"(acc[mt][nt][3])
                        : "r"(af[mt][0]), "r"(af[mt][1]), "r"(af[mt][2]), "r"(af[mt][3]),
                          "r"(bf[nt][0]), "r"(bf[nt][1]));
        }
    }

    // epilogue
    const long long rowBase = (long long)(blockIdx.y * BM + wm * 64);
    const long long colBase = blockIdx.x * BN + wn * 64;

    #pragma unroll
    for (int mt = 0; mt < 4; mt++) {
        #pragma unroll
        for (int nt = 0; nt < 8; nt++) {
            const long long r0 = rowBase + mt * 16 + g;
            const long long c0 = colBase + nt * 8 + t * 2;
            float v0 = acc[mt][nt][0] * scale;
            float v1 = acc[mt][nt][1] * scale;
            float v2 = acc[mt][nt][2] * scale;
            float v3 = acc[mt][nt][3] * scale;
            if (Cf) {
                float* Cb = Cf + (long long)blockIdx.z * sC;
                if (R) {
                    const __half* Rb = R + (long long)blockIdx.z * sR;
                    v0 += __half2float(Rb[r0 * ldr + c0]);
                    v1 += __half2float(Rb[r0 * ldr + c0 + 1]);
                    v2 += __half2float(Rb[(r0 + 8) * ldr + c0]);
                    v3 += __half2float(Rb[(r0 + 8) * ldr + c0 + 1]);
                }
                *(float2*)&Cb[r0 * ldc + c0]       = make_float2(v0, v1);
                *(float2*)&Cb[(r0 + 8) * ldc + c0] = make_float2(v2, v3);
            } else {
                __half* Cb = Ch + (long long)blockIdx.z * sC;
                *(__half2*)&Cb[r0 * ldc + c0]       = __floats2half2_rn(v0, v1);
                *(__half2*)&Cb[(r0 + 8) * ldc + c0] = __floats2half2_rn(v2, v3);
            }
        }
    }
}

// ---------------- fp32 -> fp16 conversion (8 elems/thread) ----------------
__global__ void __launch_bounds__(256) f32_to_f16(const float* __restrict__ in,
                                                  __half* __restrict__ out)
{
    long long i = ((long long)blockIdx.x * 256 + threadIdx.x) * 8;
    float4 a = *(const float4*)&in[i];
    float4 b = *(const float4*)&in[i + 4];
    __half2 h0 = __floats2half2_rn(a.x, a.y);
    __half2 h1 = __floats2half2_rn(a.z, a.w);
    __half2 h2 = __floats2half2_rn(b.x, b.y);
    __half2 h3 = __floats2half2_rn(b.z, b.w);
    uint4 u;
    u.x = *(uint32_t*)&h0; u.y = *(uint32_t*)&h1;
    u.z = *(uint32_t*)&h2; u.w = *(uint32_t*)&h3;
    *(uint4*)&out[i] = u;
}

// ------------- transpose: vt[b][n][j] = v[b][j][n], v has row stride ldv ----
__global__ void __launch_bounds__(256) transpose_v(const __half* __restrict__ v,
                                                   __half* __restrict__ vt, int ldv,
                                                   long long sIn)
{
    __shared__ __half t[32][33];
    const __half* vi = v + (long long)blockIdx.z * sIn;
    const long long bo = (long long)blockIdx.z * DIM * SEQ;
    int x = blockIdx.x * 32 + threadIdx.x;   // n
    int y = blockIdx.y * 32 + threadIdx.y;   // j
    #pragma unroll
    for (int i = 0; i < 32; i += 8)
        t[threadIdx.y + i][threadIdx.x] = vi[(long long)(y + i) * ldv + x];
    __syncthreads();
    int xo = blockIdx.y * 32 + threadIdx.x;  // j
    int yo = blockIdx.x * 32 + threadIdx.y;  // n
    #pragma unroll
    for (int i = 0; i < 32; i += 8)
        vt[bo + (long long)(yo + i) * SEQ + xo] = t[threadIdx.x][threadIdx.y + i];
}

// ---------------- row softmax (2048 cols, fp16 in/out, fp32 math) ----------
__global__ void __launch_bounds__(256) softmax_rows(__half* __restrict__ S)
{
    long long row = blockIdx.x;
    __half* p = S + row * SEQ;
    int tid = threadIdx.x;
    __shared__ float red[256];

    float v[8];
    float mx = -INFINITY;
    #pragma unroll
    for (int i = 0; i < 8; i++) { v[i] = __half2float(p[tid + i * 256]); mx = fmaxf(mx, v[i]); }
    red[tid] = mx; __syncthreads();
    #pragma unroll
    for (int s = 128; s > 0; s >>= 1) { if (tid < s) red[tid] = fmaxf(red[tid], red[tid + s]); __syncthreads(); }
    mx = red[0]; __syncthreads();

    float sum = 0.f;
    #pragma unroll
    for (int i = 0; i < 8; i++) { v[i] = __expf(v[i] - mx); sum += v[i]; }
    red[tid] = sum; __syncthreads();
    #pragma unroll
    for (int s = 128; s > 0; s >>= 1) { if (tid < s) red[tid] += red[tid + s]; __syncthreads(); }
    float inv = 1.0f / red[0];
    #pragma unroll
    for (int i = 0; i < 8; i++) p[tid + i * 256] = __float2half_rn(v[i] * inv);
}

extern "C" void kernel_launch(void* const* d_in, const int* in_sizes, int n_in,
                              void* d_out, int out_size)
{
    const float* x  = (const float*)d_in[0];
    const float* Wq = (const float*)d_in[1];
    const float* Wk = (const float*)d_in[2];
    const float* Wv = (const float*)d_in[3];
    float* out = (float*)d_out;

    __half *qkv, *vt, *s, *xh, *w;
    cudaGetSymbolAddress((void**)&qkv, g_qkv);
    cudaGetSymbolAddress((void**)&vt,  g_vt);
    cudaGetSymbolAddress((void**)&s,   g_s);
    cudaGetSymbolAddress((void**)&xh,  g_xh);
    cudaGetSymbolAddress((void**)&w,   g_w);

    cudaFuncSetAttribute(hmma_gemm_nt, cudaFuncAttributeMaxDynamicSharedMemorySize, SMEM_BYTES);

    const int M = BATCH * SEQ;            // 8192
    const int WN = 3 * DIM;               // 3072

    // fp32 -> fp16 conversion of inputs; weights concatenated Wq|Wk|Wv
    f32_to_f16<<<(M * DIM) / 2048, 256>>>(x, xh);
    f32_to_f16<<<(DIM * DIM) / 2048, 256>>>(Wq, w);
    f32_to_f16<<<(DIM * DIM) / 2048, 256>>>(Wk, w + (size_t)DIM * DIM);
    f32_to_f16<<<(DIM * DIM) / 2048, 256>>>(Wv, w + (size_t)2 * DIM * DIM);

    __half* q = qkv;
    __half* k = qkv + DIM;
    __half* v = qkv + 2 * DIM;

    // Fused QKV projection: [8192,3072] = xh @ W^T, K=1024 (16 k-tiles), fp16 out
    dim3 gP(WN / BN, M / BM, 1);   // (24, 32)
    hmma_gemm_nt<<<gP, 256, SMEM_BYTES>>>(xh, w, nullptr, nullptr, qkv,
                                          DIM, DIM, QKVLD, 0, 16, 1.0f, 0, 0, 0, 0);

    // V transpose for PV gemm (v slice of qkv, row stride 3072)
    dim3 gT(DIM / 32, SEQ / 32, BATCH);
    transpose_v<<<gT, dim3(32, 8)>>>(v, vt, QKVLD, (long long)SEQ * QKVLD);

    // Scores: per batch S = (1/32) q @ k^T, [2048,2048], K=1024, fp16 out
    dim3 gS(SEQ / BN, SEQ / BM, BATCH);   // (16, 8, 4)
    hmma_gemm_nt<<<gS, 256, SMEM_BYTES>>>(q, k, nullptr, nullptr, s,
                                          QKVLD, QKVLD, SEQ, 0, 16, 0.03125f,
                                          (long long)SEQ * QKVLD, (long long)SEQ * QKVLD, 0,
                                          (long long)SEQ * SEQ);

    softmax_rows<<<BATCH * SEQ, 256>>>(s);

    // Output: att = S @ v + v  ->  NT with B = vt [1024 x 2048], K=2048 (32 k-tiles), fp32 out
    dim3 gO(DIM / BN, SEQ / BM, BATCH);   // (8, 8, 4)
    hmma_gemm_nt<<<gO, 256, SMEM_BYTES>>>(s, vt, v, out, nullptr,
                                          SEQ, SEQ, DIM, QKVLD, 32, 1.0f,
                                          (long long)SEQ * SEQ, (long long)DIM * SEQ,
                                          (long long)SEQ * QKVLD, (long long)SEQ * DIM);
}

// round 8
// speedup vs baseline: 2.0309x; 1.1100x over previous
#include <cuda_runtime.h>
#include <cuda_fp16.h>
#include <cstdint>
#include <math.h>

// ---------------------------------------------------------------------------
// SelfAttention on GB300 (compute_103 PTX target), Round 8:
// fp16 mma.sync m16n8k16 + ldmatrix, CTA tile 128x128x64 with 4 warps
// (warp tile 64x64 unchanged), 3-slot cp.async pipeline, 2 CTAs/SM for
// cross-CTA latency overlap. Fused QKV projection.
//
// out = softmax((xWq^T)(xWk^T)^T / 32) @ (xWv^T) + (xWv^T)
// All GEMMs as NT: C[M,N] = scale * A[M,K] * B[N,K]^T (+R).
// ---------------------------------------------------------------------------

#define BATCH 4
#define SEQ   2048
#define DIM   1024
#define QKVLD 3072                                  // fused q|k|v row stride

#define BM 128
#define BN 128
#define BK 64
#define LROW 72                                     // BK + 8 pad (halves)
#define A_HALVES (BM * LROW)                        // 9216
#define B_HALVES (BN * LROW)                        // 9216
#define STAGE_HALVES (A_HALVES + B_HALVES)          // 18432
#define STAGES 3
#define SMEM_BYTES (STAGES * STAGE_HALVES * 2)      // 110592 B

__device__ __half g_qkv[(size_t)BATCH * SEQ * QKVLD];   // [8192][3072] = q|k|v
__device__ __half g_vt [(size_t)BATCH * DIM * SEQ];
__device__ __half g_s  [(size_t)BATCH * SEQ * SEQ];
__device__ __half g_xh [(size_t)BATCH * SEQ * DIM];
__device__ __half g_w  [(size_t)3 * DIM * DIM];         // Wq|Wk|Wv rows

#define CP16(dst_u32, src_ptr) \
    asm volatile("cp.async.cg.shared.global [%0], [%1], 16;" :: "r"(dst_u32), "l"(src_ptr) : "memory")
#define CP_COMMIT() asm volatile("cp.async.commit_group;" ::: "memory")
#define CP_WAIT(n)  asm volatile("cp.async.wait_group %0;" :: "n"(n) : "memory")

#define LDSM_X4(r0, r1, r2, r3, addr) \
    asm volatile("ldmatrix.sync.aligned.m8n8.x4.shared.b16 {%0,%1,%2,%3}, [%4];" \
        : "=r"(r0), "=r"(r1), "=r"(r2), "=r"(r3) : "r"(addr))

// ---------------------------------------------------------------------------
// C[M,N] = scale * A[M,K] * B[N,K]^T (+ R), fp16 in, fp32 accumulate.
// Exactly one of Cf / Ch is non-null. 128 threads, 4 warps in 2x2 grid.
// ---------------------------------------------------------------------------
__global__ void __launch_bounds__(128, 2) hmma_gemm_nt(
    const __half* __restrict__ A, const __half* __restrict__ B,
    const __half* __restrict__ R, float* __restrict__ Cf, __half* __restrict__ Ch,
    int lda, int ldb, int ldc, int ldr, int KT, float scale,
    long long sA, long long sB, long long sR, long long sC)
{
    extern __shared__ __half sm[];

    const int tid  = threadIdx.x;
    const int lane = tid & 31;
    const int wid  = tid >> 5;
    const int wm   = wid >> 1;   // 0..1  (64-row slab)
    const int wn   = wid & 1;    // 0..1  (64-col slab)
    const int g    = lane >> 2;  // 0..7
    const int t    = lane & 3;   // 0..3

    A += (long long)blockIdx.z * sA + (long long)(blockIdx.y * BM) * lda;
    B += (long long)blockIdx.z * sB + (long long)(blockIdx.x * BN) * ldb;

    const uint32_t sm_u32 = (uint32_t)__cvta_generic_to_shared(sm);

    float acc[4][8][4] = {};

    // loader: A 128x64 halves = 1024 16B-chunks (8/thr); B same (8/thr)
    auto load_stage = [&](int kt, int s) {
        const uint32_t stA = sm_u32 + (uint32_t)s * (STAGE_HALVES * 2);
        const uint32_t stB = stA + A_HALVES * 2;
        const int k0 = kt * BK;
        #pragma unroll
        for (int i = 0; i < 8; i++) {
            int f   = i * 128 + tid;      // 0..1023
            int row = f >> 3;             // 0..127
            int c8  = (f & 7) << 3;       // 0,8,..,56 (halves)
            CP16(stA + (uint32_t)(row * LROW + c8) * 2, A + (long long)row * lda + k0 + c8);
        }
        #pragma unroll
        for (int i = 0; i < 8; i++) {
            int f   = i * 128 + tid;
            int row = f >> 3;
            int c8  = (f & 7) << 3;
            CP16(stB + (uint32_t)(row * LROW + c8) * 2, B + (long long)row * ldb + k0 + c8);
        }
        CP_COMMIT();
    };

    load_stage(0, 0);
    load_stage(1, 1);

    // ldmatrix per-lane base offsets (bytes), relative to stage base
    const uint32_t aOff = (uint32_t)((wm * 64 + (lane & 15)) * LROW + ((lane >> 4) << 3)) * 2;
    const uint32_t bOff = (uint32_t)(A_HALVES
                        + (wn * 64 + (lane & 7) + ((lane & 16) >> 1)) * LROW + (lane & 8)) * 2;

    for (int kt = 0; kt < KT; kt++) {
        const int cur = kt % STAGES;

        if (kt + 1 < KT) { CP_WAIT(1); }
        else             { CP_WAIT(0); }
        __syncthreads();

        if (kt + 2 < KT) load_stage(kt + 2, (kt + 2) % STAGES);

        const uint32_t stg = sm_u32 + (uint32_t)cur * (STAGE_HALVES * 2);
        const uint32_t aLane = stg + aOff;
        const uint32_t bLane = stg + bOff;

        #pragma unroll
        for (int kk = 0; kk < 4; kk++) {
            const int kb = kk * 16;       // halves
            uint32_t af[4][4], bf[8][2];
            #pragma unroll
            for (int mt = 0; mt < 4; mt++)
                LDSM_X4(af[mt][0], af[mt][1], af[mt][2], af[mt][3],
                        aLane + (uint32_t)(mt * 16 * LROW + kb) * 2);
            #pragma unroll
            for (int p = 0; p < 4; p++)
                LDSM_X4(bf[2 * p][0], bf[2 * p][1], bf[2 * p + 1][0], bf[2 * p + 1][1],
                        bLane + (uint32_t)(p * 16 * LROW + kb) * 2);
            #pragma unroll
            for (int mt = 0; mt < 4; mt++)
                #pragma unroll
                for (int nt = 0; nt < 8; nt++)
                    asm volatile(
                        "mma.sync.aligned.m16n8k16.row.col.f32.f16.f16.f32 "
                        "{%0,%1,%2,%3}, {%4,%5,%6,%7}, {%8,%9}, {%0,%1,%2,%3};"
                        : "+f"(acc[mt][nt][0]), "+f"(acc[mt][nt][1]),
                          "+f"(acc[mt][nt][2]), "+f"(acc[mt][nt][3])
                        : "r"(af[mt][0]), "r"(af[mt][1]), "r"(af[mt][2]), "r"(af[mt][3]),
                          "r"(bf[nt][0]), "r"(bf[nt][1]));
        }
    }

    // epilogue
    const long long rowBase = (long long)(blockIdx.y * BM + wm * 64);
    const long long colBase = blockIdx.x * BN + wn * 64;

    #pragma unroll
    for (int mt = 0; mt < 4; mt++) {
        #pragma unroll
        for (int nt = 0; nt < 8; nt++) {
            const long long r0 = rowBase + mt * 16 + g;
            const long long c0 = colBase + nt * 8 + t * 2;
            float v0 = acc[mt][nt][0] * scale;
            float v1 = acc[mt][nt][1] * scale;
            float v2 = acc[mt][nt][2] * scale;
            float v3 = acc[mt][nt][3] * scale;
            if (Cf) {
                float* Cb = Cf + (long long)blockIdx.z * sC;
                if (R) {
                    const __half* Rb = R + (long long)blockIdx.z * sR;
                    v0 += __half2float(Rb[r0 * ldr + c0]);
                    v1 += __half2float(Rb[r0 * ldr + c0 + 1]);
                    v2 += __half2float(Rb[(r0 + 8) * ldr + c0]);
                    v3 += __half2float(Rb[(r0 + 8) * ldr + c0 + 1]);
                }
                *(float2*)&Cb[r0 * ldc + c0]       = make_float2(v0, v1);
                *(float2*)&Cb[(r0 + 8) * ldc + c0] = make_float2(v2, v3);
            } else {
                __half* Cb = Ch + (long long)blockIdx.z * sC;
                *(__half2*)&Cb[r0 * ldc + c0]       = __floats2half2_rn(v0, v1);
                *(__half2*)&Cb[(r0 + 8) * ldc + c0] = __floats2half2_rn(v2, v3);
            }
        }
    }
}

// ---------------- fp32 -> fp16 conversion (8 elems/thread) ----------------
__global__ void __launch_bounds__(256) f32_to_f16(const float* __restrict__ in,
                                                  __half* __restrict__ out)
{
    long long i = ((long long)blockIdx.x * 256 + threadIdx.x) * 8;
    float4 a = *(const float4*)&in[i];
    float4 b = *(const float4*)&in[i + 4];
    __half2 h0 = __floats2half2_rn(a.x, a.y);
    __half2 h1 = __floats2half2_rn(a.z, a.w);
    __half2 h2 = __floats2half2_rn(b.x, b.y);
    __half2 h3 = __floats2half2_rn(b.z, b.w);
    uint4 u;
    u.x = *(uint32_t*)&h0; u.y = *(uint32_t*)&h1;
    u.z = *(uint32_t*)&h2; u.w = *(uint32_t*)&h3;
    *(uint4*)&out[i] = u;
}

// ------------- transpose: vt[b][n][j] = v[b][j][n], v has row stride ldv ----
__global__ void __launch_bounds__(256) transpose_v(const __half* __restrict__ v,
                                                   __half* __restrict__ vt, int ldv,
                                                   long long sIn)
{
    __shared__ __half t[32][33];
    const __half* vi = v + (long long)blockIdx.z * sIn;
    const long long bo = (long long)blockIdx.z * DIM * SEQ;
    int x = blockIdx.x * 32 + threadIdx.x;   // n
    int y = blockIdx.y * 32 + threadIdx.y;   // j
    #pragma unroll
    for (int i = 0; i < 32; i += 8)
        t[threadIdx.y + i][threadIdx.x] = vi[(long long)(y + i) * ldv + x];
    __syncthreads();
    int xo = blockIdx.y * 32 + threadIdx.x;  // j
    int yo = blockIdx.x * 32 + threadIdx.y;  // n
    #pragma unroll
    for (int i = 0; i < 32; i += 8)
        vt[bo + (long long)(yo + i) * SEQ + xo] = t[threadIdx.x][threadIdx.y + i];
}

// ---------------- row softmax (2048 cols, fp16 in/out, fp32 math) ----------
__global__ void __launch_bounds__(256) softmax_rows(__half* __restrict__ S)
{
    long long row = blockIdx.x;
    __half* p = S + row * SEQ;
    int tid = threadIdx.x;
    __shared__ float red[256];

    float v[8];
    float mx = -INFINITY;
    #pragma unroll
    for (int i = 0; i < 8; i++) { v[i] = __half2float(p[tid + i * 256]); mx = fmaxf(mx, v[i]); }
    red[tid] = mx; __syncthreads();
    #pragma unroll
    for (int s = 128; s > 0; s >>= 1) { if (tid < s) red[tid] = fmaxf(red[tid], red[tid + s]); __syncthreads(); }
    mx = red[0]; __syncthreads();

    float sum = 0.f;
    #pragma unroll
    for (int i = 0; i < 8; i++) { v[i] = __expf(v[i] - mx); sum += v[i]; }
    red[tid] = sum; __syncthreads();
    #pragma unroll
    for (int s = 128; s > 0; s >>= 1) { if (tid < s) red[tid] += red[tid + s]; __syncthreads(); }
    float inv = 1.0f / red[0];
    #pragma unroll
    for (int i = 0; i < 8; i++) p[tid + i * 256] = __float2half_rn(v[i] * inv);
}

extern "C" void kernel_launch(void* const* d_in, const int* in_sizes, int n_in,
                              void* d_out, int out_size)
{
    const float* x  = (const float*)d_in[0];
    const float* Wq = (const float*)d_in[1];
    const float* Wk = (const float*)d_in[2];
    const float* Wv = (const float*)d_in[3];
    float* out = (float*)d_out;

    __half *qkv, *vt, *s, *xh, *w;
    cudaGetSymbolAddress((void**)&qkv, g_qkv);
    cudaGetSymbolAddress((void**)&vt,  g_vt);
    cudaGetSymbolAddress((void**)&s,   g_s);
    cudaGetSymbolAddress((void**)&xh,  g_xh);
    cudaGetSymbolAddress((void**)&w,   g_w);

    cudaFuncSetAttribute(hmma_gemm_nt, cudaFuncAttributeMaxDynamicSharedMemorySize, SMEM_BYTES);

    const int M = BATCH * SEQ;            // 8192
    const int WN = 3 * DIM;               // 3072

    // fp32 -> fp16 conversion of inputs; weights concatenated Wq|Wk|Wv
    f32_to_f16<<<(M * DIM) / 2048, 256>>>(x, xh);
    f32_to_f16<<<(DIM * DIM) / 2048, 256>>>(Wq, w);
    f32_to_f16<<<(DIM * DIM) / 2048, 256>>>(Wk, w + (size_t)DIM * DIM);
    f32_to_f16<<<(DIM * DIM) / 2048, 256>>>(Wv, w + (size_t)2 * DIM * DIM);

    __half* q = qkv;
    __half* k = qkv + DIM;
    __half* v = qkv + 2 * DIM;

    // Fused QKV projection: [8192,3072] = xh @ W^T, K=1024 (16 k-tiles), fp16 out
    dim3 gP(WN / BN, M / BM, 1);   // (24, 64)
    hmma_gemm_nt<<<gP, 128, SMEM_BYTES>>>(xh, w, nullptr, nullptr, qkv,
                                          DIM, DIM, QKVLD, 0, 16, 1.0f, 0, 0, 0, 0);

    // V transpose for PV gemm (v slice of qkv, row stride 3072)
    dim3 gT(DIM / 32, SEQ / 32, BATCH);
    transpose_v<<<gT, dim3(32, 8)>>>(v, vt, QKVLD, (long long)SEQ * QKVLD);

    // Scores: per batch S = (1/32) q @ k^T, [2048,2048], K=1024, fp16 out
    dim3 gS(SEQ / BN, SEQ / BM, BATCH);   // (16, 16, 4)
    hmma_gemm_nt<<<gS, 128, SMEM_BYTES>>>(q, k, nullptr, nullptr, s,
                                          QKVLD, QKVLD, SEQ, 0, 16, 0.03125f,
                                          (long long)SEQ * QKVLD, (long long)SEQ * QKVLD, 0,
                                          (long long)SEQ * SEQ);

    softmax_rows<<<BATCH * SEQ, 256>>>(s);

    // Output: att = S @ v + v  ->  NT with B = vt [1024 x 2048], K=2048 (32 k-tiles), fp32 out
    dim3 gO(DIM / BN, SEQ / BM, BATCH);   // (8, 16, 4)
    hmma_gemm_nt<<<gO, 128, SMEM_BYTES>>>(s, vt, v, out, nullptr,
                                          SEQ, SEQ, DIM, QKVLD, 32, 1.0f,
                                          (long long)SEQ * SEQ, (long long)DIM * SEQ,
                                          (long long)SEQ * QKVLD, (long long)SEQ * DIM);
}

// round 9
// speedup vs baseline: 2.1424x; 1.0549x over previous
#include <cuda_runtime.h>
#include <cuda_fp16.h>
#include <cstdint>
#include <math.h>

// ---------------------------------------------------------------------------
// SelfAttention on GB300 (compute_103 PTX target), Round 9:
// fp16 mma.sync m16n8k16 + ldmatrix, CTA 128x128x64, 4 warps, 2 CTAs/SM.
// PV GEMM is now NN (B = v in place, ldmatrix.trans) -> no transpose kernel.
// Vectorized softmax, merged weight conversion.
//
// out = softmax((xWq^T)(xWk^T)^T / 32) @ (xWv^T) + (xWv^T)
// ---------------------------------------------------------------------------

#define BATCH 4
#define SEQ   2048
#define DIM   1024
#define QKVLD 3072                                  // fused q|k|v row stride

#define BM 128
#define BN 128
#define BK 64
#define LROW 72                                     // A rows: BK + 8 pad (halves)
#define BROW 136                                    // trans-B rows: BN + 8 pad (halves)
#define A_HALVES (BM * LROW)                        // 9216
#define B_HALVES_NT (BN * LROW)                     // 9216
#define B_HALVES_NN (BK * BROW)                     // 8704
#define STAGE_HALVES (A_HALVES + B_HALVES_NT)       // 18432 (max of both variants)
#define STAGES 3
#define SMEM_BYTES (STAGES * STAGE_HALVES * 2)      // 110592 B

__device__ __half g_qkv[(size_t)BATCH * SEQ * QKVLD];   // [8192][3072] = q|k|v
__device__ __half g_s  [(size_t)BATCH * SEQ * SEQ];
__device__ __half g_xh [(size_t)BATCH * SEQ * DIM];
__device__ __half g_w  [(size_t)3 * DIM * DIM];         // Wq|Wk|Wv rows

#define CP16(dst_u32, src_ptr) \
    asm volatile("cp.async.cg.shared.global [%0], [%1], 16;" :: "r"(dst_u32), "l"(src_ptr) : "memory")
#define CP_COMMIT() asm volatile("cp.async.commit_group;" ::: "memory")
#define CP_WAIT(n)  asm volatile("cp.async.wait_group %0;" :: "n"(n) : "memory")

#define LDSM_X4(r0, r1, r2, r3, addr) \
    asm volatile("ldmatrix.sync.aligned.m8n8.x4.shared.b16 {%0,%1,%2,%3}, [%4];" \
        : "=r"(r0), "=r"(r1), "=r"(r2), "=r"(r3) : "r"(addr))
#define LDSM_X4T(r0, r1, r2, r3, addr) \
    asm volatile("ldmatrix.sync.aligned.m8n8.x4.trans.shared.b16 {%0,%1,%2,%3}, [%4];" \
        : "=r"(r0), "=r"(r1), "=r"(r2), "=r"(r3) : "r"(addr))

// ---------------------------------------------------------------------------
// TRANSB=false: C[M,N] = scale * A[M,K] * B[N,K]^T (+R)    (B K-contiguous)
// TRANSB=true : C[M,N] = scale * A[M,K] * B[K,N]   (+R)    (B N-contiguous)
// fp16 in, fp32 accumulate. Exactly one of Cf / Ch non-null.
// ---------------------------------------------------------------------------
template <bool TRANSB>
__global__ void __launch_bounds__(128, 2) hmma_gemm(
    const __half* __restrict__ A, const __half* __restrict__ B,
    const __half* __restrict__ R, float* __restrict__ Cf, __half* __restrict__ Ch,
    int lda, int ldb, int ldc, int ldr, int KT, float scale,
    long long sA, long long sB, long long sR, long long sC)
{
    extern __shared__ __half sm[];

    const int tid  = threadIdx.x;
    const int lane = tid & 31;
    const int wid  = tid >> 5;
    const int wm   = wid >> 1;   // 0..1  (64-row slab)
    const int wn   = wid & 1;    // 0..1  (64-col slab)
    const int g    = lane >> 2;  // 0..7
    const int t    = lane & 3;   // 0..3

    A += (long long)blockIdx.z * sA + (long long)(blockIdx.y * BM) * lda;
    if (TRANSB) B += (long long)blockIdx.z * sB + blockIdx.x * BN;            // column offset
    else        B += (long long)blockIdx.z * sB + (long long)(blockIdx.x * BN) * ldb;

    const uint32_t sm_u32 = (uint32_t)__cvta_generic_to_shared(sm);

    float acc[4][8][4] = {};

    auto load_stage = [&](int kt, int s) {
        const uint32_t stA = sm_u32 + (uint32_t)s * (STAGE_HALVES * 2);
        const uint32_t stB = stA + A_HALVES * 2;
        const int k0 = kt * BK;
        #pragma unroll
        for (int i = 0; i < 8; i++) {
            int f   = i * 128 + tid;      // 0..1023
            int row = f >> 3;             // 0..127
            int c8  = (f & 7) << 3;       // 0,8,..,56 (halves)
            CP16(stA + (uint32_t)(row * LROW + c8) * 2, A + (long long)row * lda + k0 + c8);
        }
        if (TRANSB) {
            // B tile [BK=64 rows (k)][BN=128 cols (n)], row stride BROW
            #pragma unroll
            for (int i = 0; i < 8; i++) {
                int f   = i * 128 + tid;      // 0..1023
                int row = f >> 4;             // 0..63  (k)
                int c8  = (f & 15) << 3;      // 0..120 (n halves)
                CP16(stB + (uint32_t)(row * BROW + c8) * 2,
                     B + (long long)(k0 + row) * ldb + c8);
            }
        } else {
            #pragma unroll
            for (int i = 0; i < 8; i++) {
                int f   = i * 128 + tid;
                int row = f >> 3;             // 0..127 (n)
                int c8  = (f & 7) << 3;       // k halves
                CP16(stB + (uint32_t)(row * LROW + c8) * 2,
                     B + (long long)row * ldb + k0 + c8);
            }
        }
        CP_COMMIT();
    };

    load_stage(0, 0);
    load_stage(1, 1);

    // ldmatrix per-lane base offsets (bytes), relative to stage base
    const uint32_t aOff = (uint32_t)((wm * 64 + (lane & 15)) * LROW + ((lane >> 4) << 3)) * 2;
    // NT: B stored [n][k]; blocks (n,k),(n,k+8),(n+8,k),(n+8,k+8)
    const uint32_t bOffNT = (uint32_t)(A_HALVES
                          + (wn * 64 + (lane & 7) + ((lane & 16) >> 1)) * LROW + (lane & 8)) * 2;
    // NN(trans): B stored [k][n]; same logical blocks, addressed by stored k-rows:
    //   row = kb + (lane&7) + (lane&8), col halves = n0 + ((lane&16)>>1)
    const uint32_t bOffNN = (uint32_t)(A_HALVES
                          + ((lane & 7) + (lane & 8)) * BROW + wn * 64 + ((lane & 16) >> 1)) * 2;

    for (int kt = 0; kt < KT; kt++) {
        const int cur = kt % STAGES;

        if (kt + 1 < KT) { CP_WAIT(1); }
        else             { CP_WAIT(0); }
        __syncthreads();

        if (kt + 2 < KT) load_stage(kt + 2, (kt + 2) % STAGES);

        const uint32_t stg = sm_u32 + (uint32_t)cur * (STAGE_HALVES * 2);
        const uint32_t aLane = stg + aOff;
        const uint32_t bLane = stg + (TRANSB ? bOffNN : bOffNT);

        #pragma unroll
        for (int kk = 0; kk < 4; kk++) {
            const int kb = kk * 16;       // halves (k)
            uint32_t af[4][4], bf[8][2];
            #pragma unroll
            for (int mt = 0; mt < 4; mt++)
                LDSM_X4(af[mt][0], af[mt][1], af[mt][2], af[mt][3],
                        aLane + (uint32_t)(mt * 16 * LROW + kb) * 2);
            #pragma unroll
            for (int p = 0; p < 4; p++) {
                if (TRANSB)
                    LDSM_X4T(bf[2 * p][0], bf[2 * p][1], bf[2 * p + 1][0], bf[2 * p + 1][1],
                             bLane + (uint32_t)(kb * BROW + p * 16) * 2);
                else
                    LDSM_X4(bf[2 * p][0], bf[2 * p][1], bf[2 * p + 1][0], bf[2 * p + 1][1],
                            bLane + (uint32_t)(p * 16 * LROW + kb) * 2);
            }
            #pragma unroll
            for (int mt = 0; mt < 4; mt++)
                #pragma unroll
                for (int nt = 0; nt < 8; nt++)
                    asm volatile(
                        "mma.sync.aligned.m16n8k16.row.col.f32.f16.f16.f32 "
                        "{%0,%1,%2,%3}, {%4,%5,%6,%7}, {%8,%9}, {%0,%1,%2,%3};"
                        : "+f"(acc[mt][nt][0]), "+f"(acc[mt][nt][1]),
                          "+f"(acc[mt][nt][2]), "+f"(acc[mt][nt][3])
                        : "r"(af[mt][0]), "r"(af[mt][1]), "r"(af[mt][2]), "r"(af[mt][3]),
                          "r"(bf[nt][0]), "r"(bf[nt][1]));
        }
    }

    // epilogue
    const long long rowBase = (long long)(blockIdx.y * BM + wm * 64);
    const long long colBase = blockIdx.x * BN + wn * 64;

    #pragma unroll
    for (int mt = 0; mt < 4; mt++) {
        #pragma unroll
        for (int nt = 0; nt < 8; nt++) {
            const long long r0 = rowBase + mt * 16 + g;
            const long long c0 = colBase + nt * 8 + t * 2;
            float v0 = acc[mt][nt][0] * scale;
            float v1 = acc[mt][nt][1] * scale;
            float v2 = acc[mt][nt][2] * scale;
            float v3 = acc[mt][nt][3] * scale;
            if (Cf) {
                float* Cb = Cf + (long long)blockIdx.z * sC;
                if (R) {
                    const __half* Rb = R + (long long)blockIdx.z * sR;
                    v0 += __half2float(Rb[r0 * ldr + c0]);
                    v1 += __half2float(Rb[r0 * ldr + c0 + 1]);
                    v2 += __half2float(Rb[(r0 + 8) * ldr + c0]);
                    v3 += __half2float(Rb[(r0 + 8) * ldr + c0 + 1]);
                }
                *(float2*)&Cb[r0 * ldc + c0]       = make_float2(v0, v1);
                *(float2*)&Cb[(r0 + 8) * ldc + c0] = make_float2(v2, v3);
            } else {
                __half* Cb = Ch + (long long)blockIdx.z * sC;
                *(__half2*)&Cb[r0 * ldc + c0]       = __floats2half2_rn(v0, v1);
                *(__half2*)&Cb[(r0 + 8) * ldc + c0] = __floats2half2_rn(v2, v3);
            }
        }
    }
}

// ---------------- fp32 -> fp16 conversion (8 elems/thread) ----------------
__global__ void __launch_bounds__(256) f32_to_f16(const float* __restrict__ in,
                                                  __half* __restrict__ out)
{
    long long i = ((long long)blockIdx.x * 256 + threadIdx.x) * 8;
    float4 a = *(const float4*)&in[i];
    float4 b = *(const float4*)&in[i + 4];
    __half2 h0 = __floats2half2_rn(a.x, a.y);
    __half2 h1 = __floats2half2_rn(a.z, a.w);
    __half2 h2 = __floats2half2_rn(b.x, b.y);
    __half2 h3 = __floats2half2_rn(b.z, b.w);
    uint4 u;
    u.x = *(uint32_t*)&h0; u.y = *(uint32_t*)&h1;
    u.z = *(uint32_t*)&h2; u.w = *(uint32_t*)&h3;
    *(uint4*)&out[i] = u;
}

// --------- 3 weight tensors -> fp16, one launch (512 blocks per tensor) ----
__global__ void __launch_bounds__(256) conv_w3(const float* __restrict__ a,
                                               const float* __restrict__ b,
                                               const float* __restrict__ c,
                                               __half* __restrict__ out)
{
    int which = blockIdx.x >> 9;                    // 0,1,2
    const float* src = (which == 0) ? a : (which == 1) ? b : c;
    __half* dst = out + (size_t)which * DIM * DIM;
    long long i = ((long long)(blockIdx.x & 511) * 256 + threadIdx.x) * 8;
    float4 u = *(const float4*)&src[i];
    float4 v = *(const float4*)&src[i + 4];
    __half2 h0 = __floats2half2_rn(u.x, u.y);
    __half2 h1 = __floats2half2_rn(u.z, u.w);
    __half2 h2 = __floats2half2_rn(v.x, v.y);
    __half2 h3 = __floats2half2_rn(v.z, v.w);
    uint4 w;
    w.x = *(uint32_t*)&h0; w.y = *(uint32_t*)&h1;
    w.z = *(uint32_t*)&h2; w.w = *(uint32_t*)&h3;
    *(uint4*)&dst[i] = w;
}

// ------- row softmax (2048 cols): vectorized uint4, shuffle reductions ------
__global__ void __launch_bounds__(256) softmax_rows(__half* __restrict__ S)
{
    long long row = blockIdx.x;
    __half* p = S + row * SEQ;
    const int tid = threadIdx.x;
    __shared__ float red[8];

    uint4 u = *(const uint4*)&p[tid * 8];
    __half2 h[4];
    h[0] = *(__half2*)&u.x; h[1] = *(__half2*)&u.y;
    h[2] = *(__half2*)&u.z; h[3] = *(__half2*)&u.w;
    float v[8];
    #pragma unroll
    for (int i = 0; i < 4; i++) {
        float2 f = __half22float2(h[i]);
        v[2 * i] = f.x; v[2 * i + 1] = f.y;
    }

    float mx = v[0];
    #pragma unroll
    for (int i = 1; i < 8; i++) mx = fmaxf(mx, v[i]);
    #pragma unroll
    for (int o = 16; o > 0; o >>= 1) mx = fmaxf(mx, __shfl_xor_sync(0xffffffff, mx, o));
    if ((tid & 31) == 0) red[tid >> 5] = mx;
    __syncthreads();
    float m0 = red[0];
    #pragma unroll
    for (int i = 1; i < 8; i++) m0 = fmaxf(m0, red[i]);
    __syncthreads();

    float sum = 0.f;
    #pragma unroll
    for (int i = 0; i < 8; i++) { v[i] = __expf(v[i] - m0); sum += v[i]; }
    #pragma unroll
    for (int o = 16; o > 0; o >>= 1) sum += __shfl_xor_sync(0xffffffff, sum, o);
    if ((tid & 31) == 0) red[tid >> 5] = sum;
    __syncthreads();
    float s0 = 0.f;
    #pragma unroll
    for (int i = 0; i < 8; i++) s0 += red[i];

    const float inv = 1.0f / s0;
    #pragma unroll
    for (int i = 0; i < 4; i++)
        h[i] = __floats2half2_rn(v[2 * i] * inv, v[2 * i + 1] * inv);
    uint4 o;
    o.x = *(uint32_t*)&h[0]; o.y = *(uint32_t*)&h[1];
    o.z = *(uint32_t*)&h[2]; o.w = *(uint32_t*)&h[3];
    *(uint4*)&p[tid * 8] = o;
}

extern "C" void kernel_launch(void* const* d_in, const int* in_sizes, int n_in,
                              void* d_out, int out_size)
{
    const float* x  = (const float*)d_in[0];
    const float* Wq = (const float*)d_in[1];
    const float* Wk = (const float*)d_in[2];
    const float* Wv = (const float*)d_in[3];
    float* out = (float*)d_out;

    __half *qkv, *s, *xh, *w;
    cudaGetSymbolAddress((void**)&qkv, g_qkv);
    cudaGetSymbolAddress((void**)&s,   g_s);
    cudaGetSymbolAddress((void**)&xh,  g_xh);
    cudaGetSymbolAddress((void**)&w,   g_w);

    cudaFuncSetAttribute(hmma_gemm<false>, cudaFuncAttributeMaxDynamicSharedMemorySize, SMEM_BYTES);
    cudaFuncSetAttribute(hmma_gemm<true>,  cudaFuncAttributeMaxDynamicSharedMemorySize, SMEM_BYTES);

    const int M = BATCH * SEQ;            // 8192
    const int WN = 3 * DIM;               // 3072

    // fp32 -> fp16 conversions
    f32_to_f16<<<(M * DIM) / 2048, 256>>>(x, xh);
    conv_w3<<<3 * 512, 256>>>(Wq, Wk, Wv, w);

    __half* q = qkv;
    __half* k = qkv + DIM;
    __half* v = qkv + 2 * DIM;

    // Fused QKV projection: [8192,3072] = xh @ W^T, K=1024 (16 k-tiles), fp16 out
    dim3 gP(WN / BN, M / BM, 1);   // (24, 64)
    hmma_gemm<false><<<gP, 128, SMEM_BYTES>>>(xh, w, nullptr, nullptr, qkv,
                                              DIM, DIM, QKVLD, 0, 16, 1.0f, 0, 0, 0, 0);

    // Scores: per batch S = (1/32) q @ k^T, [2048,2048], K=1024, fp16 out
    dim3 gS(SEQ / BN, SEQ / BM, BATCH);   // (16, 16, 4)
    hmma_gemm<false><<<gS, 128, SMEM_BYTES>>>(q, k, nullptr, nullptr, s,
                                              QKVLD, QKVLD, SEQ, 0, 16, 0.03125f,
                                              (long long)SEQ * QKVLD, (long long)SEQ * QKVLD, 0,
                                              (long long)SEQ * SEQ);

    softmax_rows<<<BATCH * SEQ, 256>>>(s);

    // Output: att = S @ v + v  (NN: B = v [2048 x 1024] n-contiguous), fp32 out
    dim3 gO(DIM / BN, SEQ / BM, BATCH);   // (8, 16, 4)
    hmma_gemm<true><<<gO, 128, SMEM_BYTES>>>(s, v, v, out, nullptr,
                                             SEQ, QKVLD, DIM, QKVLD, 32, 1.0f,
                                             (long long)SEQ * SEQ, (long long)SEQ * QKVLD,
                                             (long long)SEQ * QKVLD, (long long)SEQ * DIM);
}

// round 10
// speedup vs baseline: 2.1738x; 1.0147x over previous
#include <cuda_runtime.h>
#include <cuda_fp16.h>
#include <cstdint>
#include <math.h>

// ---------------------------------------------------------------------------
// SelfAttention on GB300 (compute_103 PTX target), Round 10:
// fp16 mma.sync m16n8k16 + ldmatrix. CTA 128x128x64 with 8 warps
// (warp tile 64x32 -> acc 64 regs, ~130 regs/thread), 2 CTAs/SM
// => 16 warps/SM for latency hiding (R9 showed regs=255 pinned occ at 11.8%,
// tensor pipe 51.7%). PV GEMM is NN via ldmatrix.trans (no V transpose).
//
// out = softmax((xWq^T)(xWk^T)^T / 32) @ (xWv^T) + (xWv^T)
// ---------------------------------------------------------------------------

#define BATCH 4
#define SEQ   2048
#define DIM   1024
#define QKVLD 3072                                  // fused q|k|v row stride

#define BM 128
#define BN 128
#define BK 64
#define NTHREADS 256
#define LROW 72                                     // A/B-NT rows: BK + 8 pad (halves)
#define BROW 136                                    // trans-B rows: BN + 8 pad (halves)
#define A_HALVES (BM * LROW)                        // 9216
#define B_HALVES_NT (BN * LROW)                     // 9216
#define STAGE_HALVES (A_HALVES + B_HALVES_NT)       // 18432
#define STAGES 3
#define SMEM_BYTES (STAGES * STAGE_HALVES * 2)      // 110592 B

__device__ __half g_qkv[(size_t)BATCH * SEQ * QKVLD];   // [8192][3072] = q|k|v
__device__ __half g_s  [(size_t)BATCH * SEQ * SEQ];
__device__ __half g_xh [(size_t)BATCH * SEQ * DIM];
__device__ __half g_w  [(size_t)3 * DIM * DIM];         // Wq|Wk|Wv rows

#define CP16(dst_u32, src_ptr) \
    asm volatile("cp.async.cg.shared.global [%0], [%1], 16;" :: "r"(dst_u32), "l"(src_ptr) : "memory")
#define CP_COMMIT() asm volatile("cp.async.commit_group;" ::: "memory")
#define CP_WAIT(n)  asm volatile("cp.async.wait_group %0;" :: "n"(n) : "memory")

#define LDSM_X4(r0, r1, r2, r3, addr) \
    asm volatile("ldmatrix.sync.aligned.m8n8.x4.shared.b16 {%0,%1,%2,%3}, [%4];" \
        : "=r"(r0), "=r"(r1), "=r"(r2), "=r"(r3) : "r"(addr))
#define LDSM_X4T(r0, r1, r2, r3, addr) \
    asm volatile("ldmatrix.sync.aligned.m8n8.x4.trans.shared.b16 {%0,%1,%2,%3}, [%4];" \
        : "=r"(r0), "=r"(r1), "=r"(r2), "=r"(r3) : "r"(addr))

// ---------------------------------------------------------------------------
// TRANSB=false: C[M,N] = scale * A[M,K] * B[N,K]^T (+R)    (B K-contiguous)
// TRANSB=true : C[M,N] = scale * A[M,K] * B[K,N]   (+R)    (B N-contiguous)
// fp16 in, fp32 accumulate. Exactly one of Cf / Ch non-null.
// 256 threads, 8 warps in 2x4 grid, warp tile 64x32.
// ---------------------------------------------------------------------------
template <bool TRANSB>
__global__ void __launch_bounds__(NTHREADS, 2) hmma_gemm(
    const __half* __restrict__ A, const __half* __restrict__ B,
    const __half* __restrict__ R, float* __restrict__ Cf, __half* __restrict__ Ch,
    int lda, int ldb, int ldc, int ldr, int KT, float scale,
    long long sA, long long sB, long long sR, long long sC)
{
    extern __shared__ __half sm[];

    const int tid  = threadIdx.x;
    const int lane = tid & 31;
    const int wid  = tid >> 5;
    const int wm   = wid >> 2;   // 0..1  (64-row slab)
    const int wn   = wid & 3;    // 0..3  (32-col slab)
    const int g    = lane >> 2;  // 0..7
    const int t    = lane & 3;   // 0..3

    A += (long long)blockIdx.z * sA + (long long)(blockIdx.y * BM) * lda;
    if (TRANSB) B += (long long)blockIdx.z * sB + blockIdx.x * BN;            // column offset
    else        B += (long long)blockIdx.z * sB + (long long)(blockIdx.x * BN) * ldb;

    const uint32_t sm_u32 = (uint32_t)__cvta_generic_to_shared(sm);

    float acc[4][4][4] = {};

    auto load_stage = [&](int kt, int s) {
        const uint32_t stA = sm_u32 + (uint32_t)s * (STAGE_HALVES * 2);
        const uint32_t stB = stA + A_HALVES * 2;
        const int k0 = kt * BK;
        #pragma unroll
        for (int i = 0; i < 4; i++) {
            int f   = i * NTHREADS + tid; // 0..1023
            int row = f >> 3;             // 0..127
            int c8  = (f & 7) << 3;       // 0,8,..,56 (halves)
            CP16(stA + (uint32_t)(row * LROW + c8) * 2, A + (long long)row * lda + k0 + c8);
        }
        if (TRANSB) {
            // B tile [BK=64 rows (k)][BN=128 cols (n)], row stride BROW
            #pragma unroll
            for (int i = 0; i < 4; i++) {
                int f   = i * NTHREADS + tid; // 0..1023
                int row = f >> 4;             // 0..63  (k)
                int c8  = (f & 15) << 3;      // 0..120 (n halves)
                CP16(stB + (uint32_t)(row * BROW + c8) * 2,
                     B + (long long)(k0 + row) * ldb + c8);
            }
        } else {
            #pragma unroll
            for (int i = 0; i < 4; i++) {
                int f   = i * NTHREADS + tid;
                int row = f >> 3;             // 0..127 (n)
                int c8  = (f & 7) << 3;       // k halves
                CP16(stB + (uint32_t)(row * LROW + c8) * 2,
                     B + (long long)row * ldb + k0 + c8);
            }
        }
        CP_COMMIT();
    };

    load_stage(0, 0);
    load_stage(1, 1);

    // ldmatrix per-lane base offsets (bytes), relative to stage base
    const uint32_t aOff = (uint32_t)((wm * 64 + (lane & 15)) * LROW + ((lane >> 4) << 3)) * 2;
    // NT: B stored [n][k]; blocks (n,k),(n,k+8),(n+8,k),(n+8,k+8)
    const uint32_t bOffNT = (uint32_t)(A_HALVES
                          + (wn * 32 + (lane & 7) + ((lane & 16) >> 1)) * LROW + (lane & 8)) * 2;
    // NN(trans): B stored [k][n]; addressed by stored k-rows:
    //   row = kb + (lane&7) + (lane&8), col halves = n0 + ((lane&16)>>1)
    const uint32_t bOffNN = (uint32_t)(A_HALVES
                          + ((lane & 7) + (lane & 8)) * BROW + wn * 32 + ((lane & 16) >> 1)) * 2;

    for (int kt = 0; kt < KT; kt++) {
        const int cur = kt % STAGES;

        if (kt + 1 < KT) { CP_WAIT(1); }
        else             { CP_WAIT(0); }
        __syncthreads();

        if (kt + 2 < KT) load_stage(kt + 2, (kt + 2) % STAGES);

        const uint32_t stg = sm_u32 + (uint32_t)cur * (STAGE_HALVES * 2);
        const uint32_t aLane = stg + aOff;
        const uint32_t bLane = stg + (TRANSB ? bOffNN : bOffNT);

        #pragma unroll
        for (int kk = 0; kk < 4; kk++) {
            const int kb = kk * 16;       // halves (k)
            uint32_t af[4][4], bf[4][2];
            #pragma unroll
            for (int mt = 0; mt < 4; mt++)
                LDSM_X4(af[mt][0], af[mt][1], af[mt][2], af[mt][3],
                        aLane + (uint32_t)(mt * 16 * LROW + kb) * 2);
            #pragma unroll
            for (int p = 0; p < 2; p++) {
                if (TRANSB)
                    LDSM_X4T(bf[2 * p][0], bf[2 * p][1], bf[2 * p + 1][0], bf[2 * p + 1][1],
                             bLane + (uint32_t)(kb * BROW + p * 16) * 2);
                else
                    LDSM_X4(bf[2 * p][0], bf[2 * p][1], bf[2 * p + 1][0], bf[2 * p + 1][1],
                            bLane + (uint32_t)(p * 16 * LROW + kb) * 2);
            }
            #pragma unroll
            for (int mt = 0; mt < 4; mt++)
                #pragma unroll
                for (int nt = 0; nt < 4; nt++)
                    asm volatile(
                        "mma.sync.aligned.m16n8k16.row.col.f32.f16.f16.f32 "
                        "{%0,%1,%2,%3}, {%4,%5,%6,%7}, {%8,%9}, {%0,%1,%2,%3};"
                        : "+f"(acc[mt][nt][0]), "+f"(acc[mt][nt][1]),
                          "+f"(acc[mt][nt][2]), "+f"(acc[mt][nt][3])
                        : "r"(af[mt][0]), "r"(af[mt][1]), "r"(af[mt][2]), "r"(af[mt][3]),
                          "r"(bf[nt][0]), "r"(bf[nt][1]));
        }
    }

    // epilogue
    const long long rowBase = (long long)(blockIdx.y * BM + wm * 64);
    const long long colBase = blockIdx.x * BN + wn * 32;

    #pragma unroll
    for (int mt = 0; mt < 4; mt++) {
        #pragma unroll
        for (int nt = 0; nt < 4; nt++) {
            const long long r0 = rowBase + mt * 16 + g;
            const long long c0 = colBase + nt * 8 + t * 2;
            float v0 = acc[mt][nt][0] * scale;
            float v1 = acc[mt][nt][1] * scale;
            float v2 = acc[mt][nt][2] * scale;
            float v3 = acc[mt][nt][3] * scale;
            if (Cf) {
                float* Cb = Cf + (long long)blockIdx.z * sC;
                if (R) {
                    const __half* Rb = R + (long long)blockIdx.z * sR;
                    v0 += __half2float(Rb[r0 * ldr + c0]);
                    v1 += __half2float(Rb[r0 * ldr + c0 + 1]);
                    v2 += __half2float(Rb[(r0 + 8) * ldr + c0]);
                    v3 += __half2float(Rb[(r0 + 8) * ldr + c0 + 1]);
                }
                *(float2*)&Cb[r0 * ldc + c0]       = make_float2(v0, v1);
                *(float2*)&Cb[(r0 + 8) * ldc + c0] = make_float2(v2, v3);
            } else {
                __half* Cb = Ch + (long long)blockIdx.z * sC;
                *(__half2*)&Cb[r0 * ldc + c0]       = __floats2half2_rn(v0, v1);
                *(__half2*)&Cb[(r0 + 8) * ldc + c0] = __floats2half2_rn(v2, v3);
            }
        }
    }
}

// ---------------- fp32 -> fp16 conversion (8 elems/thread) ----------------
__global__ void __launch_bounds__(256) f32_to_f16(const float* __restrict__ in,
                                                  __half* __restrict__ out)
{
    long long i = ((long long)blockIdx.x * 256 + threadIdx.x) * 8;
    float4 a = *(const float4*)&in[i];
    float4 b = *(const float4*)&in[i + 4];
    __half2 h0 = __floats2half2_rn(a.x, a.y);
    __half2 h1 = __floats2half2_rn(a.z, a.w);
    __half2 h2 = __floats2half2_rn(b.x, b.y);
    __half2 h3 = __floats2half2_rn(b.z, b.w);
    uint4 u;
    u.x = *(uint32_t*)&h0; u.y = *(uint32_t*)&h1;
    u.z = *(uint32_t*)&h2; u.w = *(uint32_t*)&h3;
    *(uint4*)&out[i] = u;
}

// --------- 3 weight tensors -> fp16, one launch (512 blocks per tensor) ----
__global__ void __launch_bounds__(256) conv_w3(const float* __restrict__ a,
                                               const float* __restrict__ b,
                                               const float* __restrict__ c,
                                               __half* __restrict__ out)
{
    int which = blockIdx.x >> 9;                    // 0,1,2
    const float* src = (which == 0) ? a : (which == 1) ? b : c;
    __half* dst = out + (size_t)which * DIM * DIM;
    long long i = ((long long)(blockIdx.x & 511) * 256 + threadIdx.x) * 8;
    float4 u = *(const float4*)&src[i];
    float4 v = *(const float4*)&src[i + 4];
    __half2 h0 = __floats2half2_rn(u.x, u.y);
    __half2 h1 = __floats2half2_rn(u.z, u.w);
    __half2 h2 = __floats2half2_rn(v.x, v.y);
    __half2 h3 = __floats2half2_rn(v.z, v.w);
    uint4 w;
    w.x = *(uint32_t*)&h0; w.y = *(uint32_t*)&h1;
    w.z = *(uint32_t*)&h2; w.w = *(uint32_t*)&h3;
    *(uint4*)&dst[i] = w;
}

// ------- row softmax (2048 cols): vectorized uint4, shuffle reductions ------
__global__ void __launch_bounds__(256) softmax_rows(__half* __restrict__ S)
{
    long long row = blockIdx.x;
    __half* p = S + row * SEQ;
    const int tid = threadIdx.x;
    __shared__ float red[8];

    uint4 u = *(const uint4*)&p[tid * 8];
    __half2 h[4];
    h[0] = *(__half2*)&u.x; h[1] = *(__half2*)&u.y;
    h[2] = *(__half2*)&u.z; h[3] = *(__half2*)&u.w;
    float v[8];
    #pragma unroll
    for (int i = 0; i < 4; i++) {
        float2 f = __half22float2(h[i]);
        v[2 * i] = f.x; v[2 * i + 1] = f.y;
    }

    float mx = v[0];
    #pragma unroll
    for (int i = 1; i < 8; i++) mx = fmaxf(mx, v[i]);
    #pragma unroll
    for (int o = 16; o > 0; o >>= 1) mx = fmaxf(mx, __shfl_xor_sync(0xffffffff, mx, o));
    if ((tid & 31) == 0) red[tid >> 5] = mx;
    __syncthreads();
    float m0 = red[0];
    #pragma unroll
    for (int i = 1; i < 8; i++) m0 = fmaxf(m0, red[i]);
    __syncthreads();

    float sum = 0.f;
    #pragma unroll
    for (int i = 0; i < 8; i++) { v[i] = __expf(v[i] - m0); sum += v[i]; }
    #pragma unroll
    for (int o = 16; o > 0; o >>= 1) sum += __shfl_xor_sync(0xffffffff, sum, o);
    if ((tid & 31) == 0) red[tid >> 5] = sum;
    __syncthreads();
    float s0 = 0.f;
    #pragma unroll
    for (int i = 0; i < 8; i++) s0 += red[i];

    const float inv = 1.0f / s0;
    #pragma unroll
    for (int i = 0; i < 4; i++)
        h[i] = __floats2half2_rn(v[2 * i] * inv, v[2 * i + 1] * inv);
    uint4 o;
    o.x = *(uint32_t*)&h[0]; o.y = *(uint32_t*)&h[1];
    o.z = *(uint32_t*)&h[2]; o.w = *(uint32_t*)&h[3];
    *(uint4*)&p[tid * 8] = o;
}

extern "C" void kernel_launch(void* const* d_in, const int* in_sizes, int n_in,
                              void* d_out, int out_size)
{
    const float* x  = (const float*)d_in[0];
    const float* Wq = (const float*)d_in[1];
    const float* Wk = (const float*)d_in[2];
    const float* Wv = (const float*)d_in[3];
    float* out = (float*)d_out;

    __half *qkv, *s, *xh, *w;
    cudaGetSymbolAddress((void**)&qkv, g_qkv);
    cudaGetSymbolAddress((void**)&s,   g_s);
    cudaGetSymbolAddress((void**)&xh,  g_xh);
    cudaGetSymbolAddress((void**)&w,   g_w);

    cudaFuncSetAttribute(hmma_gemm<false>, cudaFuncAttributeMaxDynamicSharedMemorySize, SMEM_BYTES);
    cudaFuncSetAttribute(hmma_gemm<true>,  cudaFuncAttributeMaxDynamicSharedMemorySize, SMEM_BYTES);

    const int M = BATCH * SEQ;            // 8192
    const int WN = 3 * DIM;               // 3072

    // fp32 -> fp16 conversions
    f32_to_f16<<<(M * DIM) / 2048, 256>>>(x, xh);
    conv_w3<<<3 * 512, 256>>>(Wq, Wk, Wv, w);

    __half* q = qkv;
    __half* k = qkv + DIM;
    __half* v = qkv + 2 * DIM;

    // Fused QKV projection: [8192,3072] = xh @ W^T, K=1024 (16 k-tiles), fp16 out
    dim3 gP(WN / BN, M / BM, 1);   // (24, 64)
    hmma_gemm<false><<<gP, NTHREADS, SMEM_BYTES>>>(xh, w, nullptr, nullptr, qkv,
                                                   DIM, DIM, QKVLD, 0, 16, 1.0f, 0, 0, 0, 0);

    // Scores: per batch S = (1/32) q @ k^T, [2048,2048], K=1024, fp16 out
    dim3 gS(SEQ / BN, SEQ / BM, BATCH);   // (16, 16, 4)
    hmma_gemm<false><<<gS, NTHREADS, SMEM_BYTES>>>(q, k, nullptr, nullptr, s,
                                                   QKVLD, QKVLD, SEQ, 0, 16, 0.03125f,
                                                   (long long)SEQ * QKVLD, (long long)SEQ * QKVLD, 0,
                                                   (long long)SEQ * SEQ);

    softmax_rows<<<BATCH * SEQ, 256>>>(s);

    // Output: att = S @ v + v  (NN: B = v [2048 x 1024] n-contiguous), fp32 out
    dim3 gO(DIM / BN, SEQ / BM, BATCH);   // (8, 16, 4)
    hmma_gemm<true><<<gO, NTHREADS, SMEM_BYTES>>>(s, v, v, out, nullptr,
                                                  SEQ, QKVLD, DIM, QKVLD, 32, 1.0f,
                                                  (long long)SEQ * SEQ, (long long)SEQ * QKVLD,
                                                  (long long)SEQ * QKVLD, (long long)SEQ * DIM);
}